// round 1
// baseline (speedup 1.0000x reference)
#include <cuda_runtime.h>
#include <math.h>

// Problem constants
#define NROWS   100352          // B*H*W = B*nW*N = 32*56*56
#define CDIM    192
#define HID     768
#define QKVDIM  576
#define NHEAD   6
#define HDIM    32
#define NTOK    49
#define NWIN    64

// -------- scratch (device globals; no allocation allowed) --------
__device__ float g_xw  [(size_t)NROWS * CDIM];    // ln1 + shift + window-partitioned
__device__ float g_qkv [(size_t)NROWS * QKVDIM];
__device__ float g_ao  [(size_t)NROWS * CDIM];    // attention output (window layout)
__device__ float g_proj[(size_t)NROWS * CDIM];    // proj output (window layout)
__device__ float g_x1  [(size_t)NROWS * CDIM];    // residual 1 (image layout)
__device__ float g_h   [(size_t)NROWS * HID];     // MLP hidden

// ---------------------------------------------------------------
// LayerNorm. mode==1: read via shift+window mapping (ln1),
// mode==0: identity row mapping (ln2). One warp per row of 192.
// ---------------------------------------------------------------
__global__ void ln_kernel(const float* __restrict__ x,
                          const float* __restrict__ gw,
                          const float* __restrict__ gb,
                          float* __restrict__ out, int mode)
{
    int warp = (blockIdx.x * blockDim.x + threadIdx.x) >> 5;
    int lane = threadIdx.x & 31;
    if (warp >= NROWS) return;

    const float* src;
    if (mode == 1) {
        int bb  = warp / 3136;
        int rem = warp % 3136;
        int win = rem / NTOK;
        int n   = rem % NTOK;
        int h_s = (win >> 3) * 7 + n / 7;
        int w_s = (win & 7) * 7 + n % 7;
        int hh = (h_s + 3) % 56;          // roll(-3): shifted[i] = x[(i+3)%56]
        int ww = (w_s + 3) % 56;
        src = x + ((size_t)bb * 3136 + hh * 56 + ww) * CDIM;
    } else {
        src = x + (size_t)warp * CDIM;
    }

    float v[6];
    float s = 0.f, sq = 0.f;
    #pragma unroll
    for (int k = 0; k < 6; k++) {
        v[k] = src[lane + 32 * k];
        s += v[k];
        sq += v[k] * v[k];
    }
    #pragma unroll
    for (int o = 16; o; o >>= 1) {
        s  += __shfl_xor_sync(0xFFFFFFFFu, s, o);
        sq += __shfl_xor_sync(0xFFFFFFFFu, sq, o);
    }
    float mu  = s * (1.f / 192.f);
    float var = sq * (1.f / 192.f) - mu * mu;
    float rs  = rsqrtf(var + 1e-5f);

    float* dst = out + (size_t)warp * CDIM;
    #pragma unroll
    for (int k = 0; k < 6; k++) {
        int c = lane + 32 * k;
        dst[c] = (v[k] - mu) * rs * gw[c] + gb[c];
    }
}

// ---------------------------------------------------------------
// Tiled SGEMM: C[M,N] = A[M,K] @ W[K,N] + bias, optional epilogue.
// BM=128, BN=64, BK=16, 256 threads, 8x4 per-thread microtile.
// M % 128 == 0, N % 64 == 0, K % 16 == 0 (all hold here).
// EPI: 0 = none, 1 = exact GELU, 2 = add residual (res, same layout).
// ---------------------------------------------------------------
template <int EPI>
__global__ void sgemm_kernel(const float* __restrict__ A,
                             const float* __restrict__ W,
                             const float* __restrict__ bias,
                             float* __restrict__ C,
                             const float* __restrict__ res,
                             int M, int N, int K)
{
    __shared__ float As[16][128];
    __shared__ float Bs[16][64];

    const int t  = threadIdx.x;
    const int bm = blockIdx.y * 128;
    const int bn = blockIdx.x * 64;
    const int tx = t & 15;   // N direction: 16 * 4 = 64
    const int ty = t >> 4;   // M direction: 16 * 8 = 128

    float acc[8][4] = {};

    for (int k0 = 0; k0 < K; k0 += 16) {
        // A tile: 128x16 = 512 float4 loads; 2 per thread, stored transposed.
        #pragma unroll
        for (int l = 0; l < 2; l++) {
            int f   = t + l * 256;
            int row = f >> 2;
            int cg  = f & 3;
            float4 a4 = *(const float4*)(A + (size_t)(bm + row) * K + k0 + cg * 4);
            As[cg * 4 + 0][row] = a4.x;
            As[cg * 4 + 1][row] = a4.y;
            As[cg * 4 + 2][row] = a4.z;
            As[cg * 4 + 3][row] = a4.w;
        }
        // B tile: 16x64 = 256 float4 loads; 1 per thread.
        {
            int rowb = t >> 4;
            int cgb  = t & 15;
            *(float4*)(&Bs[rowb][cgb * 4]) =
                *(const float4*)(W + (size_t)(k0 + rowb) * N + bn + cgb * 4);
        }
        __syncthreads();

        #pragma unroll
        for (int kk = 0; kk < 16; kk++) {
            float4 a0 = *(const float4*)(&As[kk][ty * 8]);
            float4 a1 = *(const float4*)(&As[kk][ty * 8 + 4]);
            float4 b0 = *(const float4*)(&Bs[kk][tx * 4]);
            float av[8] = {a0.x, a0.y, a0.z, a0.w, a1.x, a1.y, a1.z, a1.w};
            float bv[4] = {b0.x, b0.y, b0.z, b0.w};
            #pragma unroll
            for (int i = 0; i < 8; i++)
                #pragma unroll
                for (int j = 0; j < 4; j++)
                    acc[i][j] += av[i] * bv[j];
        }
        __syncthreads();
    }

    // Epilogue: 4 consecutive columns per thread -> float4 store.
    #pragma unroll
    for (int i = 0; i < 8; i++) {
        int row = bm + ty * 8 + i;
        int col = bn + tx * 4;
        size_t o = (size_t)row * N + col;
        float4 v;
        float* vp = &v.x;
        #pragma unroll
        for (int j = 0; j < 4; j++) {
            float val = acc[i][j] + bias[col + j];
            if (EPI == 1) val = 0.5f * val * (1.f + erff(val * 0.70710678118654752f));
            vp[j] = val;
        }
        if (EPI == 2) {
            float4 r = *(const float4*)(res + o);
            v.x += r.x; v.y += r.y; v.z += r.z; v.w += r.w;
        }
        *(float4*)(C + o) = v;
    }
}

// ---------------------------------------------------------------
// Windowed attention: one block per (batch, window, head).
// N=49 tokens, hd=32. scores + rel-pos bias + shift mask + softmax + AV.
// ---------------------------------------------------------------
__global__ void attn_kernel(const float* __restrict__ qkv,
                            const float* __restrict__ rpb_table,
                            float* __restrict__ ao)
{
    __shared__ float qs[NTOK][HDIM + 1];
    __shared__ float ks[NTOK][HDIM + 1];
    __shared__ float vs[NTOK][HDIM + 1];
    __shared__ float sc[NTOK][NTOK + 1];

    const int bid  = blockIdx.x;
    const int head = bid % NHEAD;
    const int win  = (bid / NHEAD) % NWIN;
    const int bb   = bid / (NHEAD * NWIN);
    const int tid  = threadIdx.x;

    const size_t baserow = (size_t)(bb * NWIN + win) * NTOK;

    // Load q/k/v tiles for this head
    for (int idx = tid; idx < NTOK * HDIM; idx += 256) {
        int n = idx >> 5, d = idx & 31;
        const float* p = qkv + (baserow + n) * QKVDIM + head * HDIM + d;
        qs[n][d] = p[0];
        ks[n][d] = p[CDIM];
        vs[n][d] = p[2 * CDIM];
    }
    __syncthreads();

    const int wh = win >> 3, ww = win & 7;
    const float scale = 0.17677669529663687f;   // 32^-0.5

    // Scores + bias + mask
    for (int idx = tid; idx < NTOK * NTOK; idx += 256) {
        int i = idx / NTOK, j = idx % NTOK;
        float s = 0.f;
        #pragma unroll
        for (int d = 0; d < HDIM; d++) s += qs[i][d] * ks[j][d];
        s *= scale;

        int ih = i / 7, iw = i % 7, jh = j / 7, jw = j % 7;
        s += rpb_table[((ih - jh + 6) * 13 + (iw - jw + 6)) * NHEAD + head];

        // shift mask: region ids on shifted coords, boundaries at 49 / 53
        int hi = wh * 7 + ih, wi = ww * 7 + iw;
        int hj = wh * 7 + jh, wj = ww * 7 + jw;
        int ri = (hi < 49 ? 0 : (hi < 53 ? 1 : 2)) * 3 + (wi < 49 ? 0 : (wi < 53 ? 1 : 2));
        int rj = (hj < 49 ? 0 : (hj < 53 ? 1 : 2)) * 3 + (wj < 49 ? 0 : (wj < 53 ? 1 : 2));
        if (ri != rj) s -= 100.f;

        sc[i][j] = s;
    }
    __syncthreads();

    // Softmax: one warp per row
    int warp = tid >> 5, lane = tid & 31;
    for (int i = warp; i < NTOK; i += 8) {
        float m = -1e30f;
        for (int j = lane; j < NTOK; j += 32) m = fmaxf(m, sc[i][j]);
        #pragma unroll
        for (int o = 16; o; o >>= 1) m = fmaxf(m, __shfl_xor_sync(0xFFFFFFFFu, m, o));
        float sum = 0.f;
        for (int j = lane; j < NTOK; j += 32) {
            float e = expf(sc[i][j] - m);
            sc[i][j] = e;
            sum += e;
        }
        #pragma unroll
        for (int o = 16; o; o >>= 1) sum += __shfl_xor_sync(0xFFFFFFFFu, sum, o);
        float inv = 1.f / sum;
        for (int j = lane; j < NTOK; j += 32) sc[i][j] *= inv;
    }
    __syncthreads();

    // out = attn @ v
    for (int idx = tid; idx < NTOK * HDIM; idx += 256) {
        int i = idx >> 5, d = idx & 31;
        float s = 0.f;
        #pragma unroll
        for (int j = 0; j < NTOK; j++) s += sc[i][j] * vs[j][d];
        ao[(baserow + i) * CDIM + head * HDIM + d] = s;
    }
}

// ---------------------------------------------------------------
// Un-window + un-shift the proj output and add shortcut:
// x1[b, (h_s+3)%56, (w_s+3)%56, :] = x[...] + proj[row, :]
// ---------------------------------------------------------------
__global__ void scatter_add_kernel(const float* __restrict__ p,
                                   const float* __restrict__ x,
                                   float* __restrict__ out)
{
    int idx = blockIdx.x * blockDim.x + threadIdx.x;
    if (idx >= NROWS * 48) return;
    int row = idx / 48, c4 = idx % 48;
    int bb  = row / 3136;
    int rem = row % 3136;
    int win = rem / NTOK;
    int n   = rem % NTOK;
    int h_s = (win >> 3) * 7 + n / 7;
    int w_s = (win & 7) * 7 + n % 7;
    int hh = (h_s + 3) % 56;
    int ww = (w_s + 3) % 56;
    size_t dsto = ((size_t)bb * 3136 + hh * 56 + ww) * CDIM + c4 * 4;
    float4 a = *(const float4*)(p + (size_t)row * CDIM + c4 * 4);
    float4 s = *(const float4*)(x + dsto);
    a.x += s.x; a.y += s.y; a.z += s.z; a.w += s.w;
    *(float4*)(out + dsto) = a;
}

// ---------------------------------------------------------------
extern "C" void kernel_launch(void* const* d_in, const int* in_sizes, int n_in,
                              void* d_out, int out_size)
{
    const float* x       = (const float*)d_in[0];
    const float* norm1_g = (const float*)d_in[1];
    const float* norm1_b = (const float*)d_in[2];
    const float* qkv_w   = (const float*)d_in[3];
    const float* qkv_b   = (const float*)d_in[4];
    const float* rpb_t   = (const float*)d_in[5];
    const float* proj_w  = (const float*)d_in[6];
    const float* proj_b  = (const float*)d_in[7];
    const float* norm2_g = (const float*)d_in[8];
    const float* norm2_b = (const float*)d_in[9];
    const float* fc1_w   = (const float*)d_in[10];
    const float* fc1_b   = (const float*)d_in[11];
    const float* fc2_w   = (const float*)d_in[12];
    const float* fc2_b   = (const float*)d_in[13];
    float* out = (float*)d_out;

    float *xw, *qkvbuf, *ao, *proj, *x1, *hbuf;
    cudaGetSymbolAddress((void**)&xw,     g_xw);
    cudaGetSymbolAddress((void**)&qkvbuf, g_qkv);
    cudaGetSymbolAddress((void**)&ao,     g_ao);
    cudaGetSymbolAddress((void**)&proj,   g_proj);
    cudaGetSymbolAddress((void**)&x1,     g_x1);
    cudaGetSymbolAddress((void**)&hbuf,   g_h);

    const int lnGrid = (NROWS + 7) / 8;   // 8 warps per 256-thread block

    // 1. LN1 + shift + window partition
    ln_kernel<<<lnGrid, 256>>>(x, norm1_g, norm1_b, xw, 1);

    // 2. QKV GEMM [100352,192] @ [192,576]
    sgemm_kernel<0><<<dim3(QKVDIM / 64, NROWS / 128), 256>>>(
        xw, qkv_w, qkv_b, qkvbuf, nullptr, NROWS, QKVDIM, CDIM);

    // 3. Windowed attention
    attn_kernel<<<32 * NWIN * NHEAD, 256>>>(qkvbuf, rpb_t, ao);

    // 4. Projection GEMM [100352,192] @ [192,192]
    sgemm_kernel<0><<<dim3(CDIM / 64, NROWS / 128), 256>>>(
        ao, proj_w, proj_b, proj, nullptr, NROWS, CDIM, CDIM);

    // 5. Un-window + un-shift + residual
    scatter_add_kernel<<<(NROWS * 48 + 255) / 256, 256>>>(proj, x, x1);

    // 6. LN2 (reuse xw buffer)
    ln_kernel<<<lnGrid, 256>>>(x1, norm2_g, norm2_b, xw, 0);

    // 7. FC1 + exact GELU [100352,192] @ [192,768]
    sgemm_kernel<1><<<dim3(HID / 64, NROWS / 128), 256>>>(
        xw, fc1_w, fc1_b, hbuf, nullptr, NROWS, HID, CDIM);

    // 8. FC2 + residual [100352,768] @ [768,192] -> d_out
    sgemm_kernel<2><<<dim3(CDIM / 64, NROWS / 128), 256>>>(
        hbuf, fc2_w, fc2_b, out, x1, NROWS, CDIM, HID);
}

// round 3
// speedup vs baseline: 1.9835x; 1.9835x over previous
#include <cuda_runtime.h>
#include <math.h>
#include <stdint.h>

// Problem constants
#define NROWS   100352          // B*H*W = B*nW*N = 32*56*56
#define CDIM    192
#define HID     768
#define QKVDIM  576
#define NHEAD   6
#define HDIM    32
#define NTOK    49
#define NWIN    64

// -------- scratch (device globals; no allocation allowed) --------
__device__ float g_xw  [(size_t)NROWS * CDIM];
__device__ float g_qkv [(size_t)NROWS * QKVDIM];
__device__ float g_ao  [(size_t)NROWS * CDIM];
__device__ float g_proj[(size_t)NROWS * CDIM];
__device__ float g_x1  [(size_t)NROWS * CDIM];
__device__ float g_h   [(size_t)NROWS * HID];

// ---------------------------------------------------------------
// LayerNorm (mode 1: shift+window gather for ln1; mode 0: identity)
// ---------------------------------------------------------------
__global__ void ln_kernel(const float* __restrict__ x,
                          const float* __restrict__ gw,
                          const float* __restrict__ gb,
                          float* __restrict__ out, int mode)
{
    int warp = (blockIdx.x * blockDim.x + threadIdx.x) >> 5;
    int lane = threadIdx.x & 31;
    if (warp >= NROWS) return;

    const float* src;
    if (mode == 1) {
        int bb  = warp / 3136;
        int rem = warp % 3136;
        int win = rem / NTOK;
        int n   = rem % NTOK;
        int h_s = (win >> 3) * 7 + n / 7;
        int w_s = (win & 7) * 7 + n % 7;
        int hh = (h_s + 3) % 56;
        int ww = (w_s + 3) % 56;
        src = x + ((size_t)bb * 3136 + hh * 56 + ww) * CDIM;
    } else {
        src = x + (size_t)warp * CDIM;
    }

    float v[6];
    float s = 0.f, sq = 0.f;
    #pragma unroll
    for (int k = 0; k < 6; k++) {
        v[k] = src[lane + 32 * k];
        s += v[k];
        sq += v[k] * v[k];
    }
    #pragma unroll
    for (int o = 16; o; o >>= 1) {
        s  += __shfl_xor_sync(0xFFFFFFFFu, s, o);
        sq += __shfl_xor_sync(0xFFFFFFFFu, sq, o);
    }
    float mu  = s * (1.f / 192.f);
    float var = sq * (1.f / 192.f) - mu * mu;
    float rs  = rsqrtf(var + 1e-5f);

    float* dst = out + (size_t)warp * CDIM;
    #pragma unroll
    for (int k = 0; k < 6; k++) {
        int c = lane + 32 * k;
        dst[c] = (v[k] - mu) * rs * gw[c] + gb[c];
    }
}

// ---------------------------------------------------------------
// TF32 tensor-core GEMM: C[M,N] = A[M,K] @ W[K,N] + bias (+epilogue)
// BM=128, BN=64, BK=16, 3-stage cp.async pipeline, 256 threads.
// 8 warps in 4(M) x 2(N); warp tile 32x32 via mma.m16n8k8.tf32.
// EPI: 0 none, 1 exact GELU, 2 add residual.
// ---------------------------------------------------------------
#define AS_STRIDE 20          // 16 k + 4 pad  -> conflict-free A frag loads
#define BS_STRIDE 72          // 64 n + 8 pad  -> conflict-free B frag loads
#define A_F       (128 * AS_STRIDE)   // 2560 floats
#define B_F       (16 * BS_STRIDE)    // 1152 floats
#define STAGE_F   (A_F + B_F)         // 3712 floats
#define STAGES    3

__device__ __forceinline__ void cp16(uint32_t dst, const void* src) {
    asm volatile("cp.async.cg.shared.global [%0], [%1], 16;" :: "r"(dst), "l"(src));
}
__device__ __forceinline__ void cp_commit() {
    asm volatile("cp.async.commit_group;");
}
__device__ __forceinline__ void cp_wait2() {
    asm volatile("cp.async.wait_group 2;" ::: "memory");
}

__device__ __forceinline__ void mma_tf32(float d[4], const uint32_t a[4], const uint32_t b[2]) {
    asm volatile(
        "mma.sync.aligned.m16n8k8.row.col.f32.tf32.tf32.f32 "
        "{%0,%1,%2,%3}, {%4,%5,%6,%7}, {%8,%9}, {%0,%1,%2,%3};\n"
        : "+f"(d[0]), "+f"(d[1]), "+f"(d[2]), "+f"(d[3])
        : "r"(a[0]), "r"(a[1]), "r"(a[2]), "r"(a[3]), "r"(b[0]), "r"(b[1]));
}

template <int EPI>
__global__ void __launch_bounds__(256)
mma_gemm(const float* __restrict__ A,
         const float* __restrict__ W,
         const float* __restrict__ bias,
         float* __restrict__ C,
         const float* __restrict__ res,
         int M, int N, int K)
{
    __shared__ float sm[STAGES * STAGE_F];

    const int t    = threadIdx.x;
    const int bm   = blockIdx.y * 128;
    const int bn   = blockIdx.x * 64;
    const int lane = t & 31;
    const int w    = t >> 5;
    const int g    = lane >> 2;
    const int tig  = lane & 3;
    const int wm   = (w & 3) * 32;
    const int wn   = (w >> 2) * 32;

    // cp.async source mappings
    const int arow = t >> 2;          // rows arow and arow+64
    const int ac   = (t & 3) * 4;     // 4 float4s cover 16 k
    const int brow = t >> 4;
    const int bc   = (t & 15) * 4;

    float acc[2][4][4] = {};

    auto issue = [&](int stage, int kt) {
        float* As = sm + stage * STAGE_F;
        float* Bs = As + A_F;
        const float* ag = A + (size_t)(bm + arow) * K + kt * 16 + ac;
        uint32_t ad = (uint32_t)__cvta_generic_to_shared(As + arow * AS_STRIDE + ac);
        cp16(ad, ag);
        cp16(ad + 64 * AS_STRIDE * 4, ag + (size_t)64 * K);
        const float* wg = W + (size_t)(kt * 16 + brow) * N + bn + bc;
        cp16((uint32_t)__cvta_generic_to_shared(Bs + brow * BS_STRIDE + bc), wg);
    };

    auto compute = [&](int stage) {
        const float* As = sm + stage * STAGE_F;
        const float* Bs = As + A_F;
        #pragma unroll
        for (int ks = 0; ks < 16; ks += 8) {
            uint32_t a[2][4], b[4][2];
            #pragma unroll
            for (int mi = 0; mi < 2; mi++) {
                const float* ap = As + (wm + mi * 16) * AS_STRIDE + ks;
                a[mi][0] = __float_as_uint(ap[g * AS_STRIDE + tig]);
                a[mi][1] = __float_as_uint(ap[(g + 8) * AS_STRIDE + tig]);
                a[mi][2] = __float_as_uint(ap[g * AS_STRIDE + tig + 4]);
                a[mi][3] = __float_as_uint(ap[(g + 8) * AS_STRIDE + tig + 4]);
            }
            #pragma unroll
            for (int ni = 0; ni < 4; ni++) {
                const float* bp = Bs + (ks + tig) * BS_STRIDE + wn + ni * 8 + g;
                b[ni][0] = __float_as_uint(bp[0]);
                b[ni][1] = __float_as_uint(bp[4 * BS_STRIDE]);
            }
            #pragma unroll
            for (int mi = 0; mi < 2; mi++)
                #pragma unroll
                for (int ni = 0; ni < 4; ni++)
                    mma_tf32(acc[mi][ni], a[mi], b[ni]);
        }
    };

    const int KT = K >> 4;
    issue(0, 0); cp_commit();
    issue(1, 1); cp_commit();

    for (int kt = 0; kt < KT; kt++) {
        if (kt + 2 < KT) issue((kt + 2) % 3, kt + 2);
        cp_commit();
        cp_wait2();
        __syncthreads();
        compute(kt % 3);
        __syncthreads();
    }

    // Epilogue: each (mi,ni) tile -> two float2 stores (rows g, g+8)
    #pragma unroll
    for (int mi = 0; mi < 2; mi++) {
        #pragma unroll
        for (int ni = 0; ni < 4; ni++) {
            int col = bn + wn + ni * 8 + tig * 2;
            float2 bia = *(const float2*)(bias + col);
            int r0 = bm + wm + mi * 16 + g;
            #pragma unroll
            for (int half = 0; half < 2; half++) {
                int row = r0 + half * 8;
                float v0 = acc[mi][ni][half * 2 + 0] + bia.x;
                float v1 = acc[mi][ni][half * 2 + 1] + bia.y;
                if (EPI == 1) {
                    v0 = 0.5f * v0 * (1.f + erff(v0 * 0.70710678118654752f));
                    v1 = 0.5f * v1 * (1.f + erff(v1 * 0.70710678118654752f));
                }
                size_t o = (size_t)row * N + col;
                if (EPI == 2) {
                    float2 r = *(const float2*)(res + o);
                    v0 += r.x; v1 += r.y;
                }
                float2 out2 = make_float2(v0, v1);
                *(float2*)(C + o) = out2;
            }
        }
    }
}

// ---------------------------------------------------------------
// Windowed attention: one block per (batch, window, head).
// ---------------------------------------------------------------
__global__ void attn_kernel(const float* __restrict__ qkv,
                            const float* __restrict__ rpb_table,
                            float* __restrict__ ao)
{
    __shared__ float qs[NTOK][HDIM + 1];
    __shared__ float ks[NTOK][HDIM + 1];
    __shared__ float vs[NTOK][HDIM + 1];
    __shared__ float sc[NTOK][NTOK + 1];

    const int bid  = blockIdx.x;
    const int head = bid % NHEAD;
    const int win  = (bid / NHEAD) % NWIN;
    const int bb   = bid / (NHEAD * NWIN);
    const int tid  = threadIdx.x;

    const size_t baserow = (size_t)(bb * NWIN + win) * NTOK;

    for (int idx = tid; idx < NTOK * HDIM; idx += 256) {
        int n = idx >> 5, d = idx & 31;
        const float* p = qkv + (baserow + n) * QKVDIM + head * HDIM + d;
        qs[n][d] = p[0];
        ks[n][d] = p[CDIM];
        vs[n][d] = p[2 * CDIM];
    }
    __syncthreads();

    const int wh = win >> 3, ww = win & 7;
    const float scale = 0.17677669529663687f;

    for (int idx = tid; idx < NTOK * NTOK; idx += 256) {
        int i = idx / NTOK, j = idx % NTOK;
        float s = 0.f;
        #pragma unroll
        for (int d = 0; d < HDIM; d++) s += qs[i][d] * ks[j][d];
        s *= scale;

        int ih = i / 7, iw = i % 7, jh = j / 7, jw = j % 7;
        s += rpb_table[((ih - jh + 6) * 13 + (iw - jw + 6)) * NHEAD + head];

        int hi = wh * 7 + ih, wi = ww * 7 + iw;
        int hj = wh * 7 + jh, wj = ww * 7 + jw;
        int ri = (hi < 49 ? 0 : (hi < 53 ? 1 : 2)) * 3 + (wi < 49 ? 0 : (wi < 53 ? 1 : 2));
        int rj = (hj < 49 ? 0 : (hj < 53 ? 1 : 2)) * 3 + (wj < 49 ? 0 : (wj < 53 ? 1 : 2));
        if (ri != rj) s -= 100.f;

        sc[i][j] = s;
    }
    __syncthreads();

    int warp = tid >> 5, lane = tid & 31;
    for (int i = warp; i < NTOK; i += 8) {
        float m = -1e30f;
        for (int j = lane; j < NTOK; j += 32) m = fmaxf(m, sc[i][j]);
        #pragma unroll
        for (int o = 16; o; o >>= 1) m = fmaxf(m, __shfl_xor_sync(0xFFFFFFFFu, m, o));
        float sum = 0.f;
        for (int j = lane; j < NTOK; j += 32) {
            float e = expf(sc[i][j] - m);
            sc[i][j] = e;
            sum += e;
        }
        #pragma unroll
        for (int o = 16; o; o >>= 1) sum += __shfl_xor_sync(0xFFFFFFFFu, sum, o);
        float inv = 1.f / sum;
        for (int j = lane; j < NTOK; j += 32) sc[i][j] *= inv;
    }
    __syncthreads();

    for (int idx = tid; idx < NTOK * HDIM; idx += 256) {
        int i = idx >> 5, d = idx & 31;
        float s = 0.f;
        #pragma unroll
        for (int j = 0; j < NTOK; j++) s += sc[i][j] * vs[j][d];
        ao[(baserow + i) * CDIM + head * HDIM + d] = s;
    }
}

// ---------------------------------------------------------------
// Un-window + un-shift + residual add
// ---------------------------------------------------------------
__global__ void scatter_add_kernel(const float* __restrict__ p,
                                   const float* __restrict__ x,
                                   float* __restrict__ out)
{
    int idx = blockIdx.x * blockDim.x + threadIdx.x;
    if (idx >= NROWS * 48) return;
    int row = idx / 48, c4 = idx % 48;
    int bb  = row / 3136;
    int rem = row % 3136;
    int win = rem / NTOK;
    int n   = rem % NTOK;
    int h_s = (win >> 3) * 7 + n / 7;
    int w_s = (win & 7) * 7 + n % 7;
    int hh = (h_s + 3) % 56;
    int ww = (w_s + 3) % 56;
    size_t dsto = ((size_t)bb * 3136 + hh * 56 + ww) * CDIM + c4 * 4;
    float4 a = *(const float4*)(p + (size_t)row * CDIM + c4 * 4);
    float4 s = *(const float4*)(x + dsto);
    a.x += s.x; a.y += s.y; a.z += s.z; a.w += s.w;
    *(float4*)(out + dsto) = a;
}

// ---------------------------------------------------------------
extern "C" void kernel_launch(void* const* d_in, const int* in_sizes, int n_in,
                              void* d_out, int out_size)
{
    const float* x       = (const float*)d_in[0];
    const float* norm1_g = (const float*)d_in[1];
    const float* norm1_b = (const float*)d_in[2];
    const float* qkv_w   = (const float*)d_in[3];
    const float* qkv_b   = (const float*)d_in[4];
    const float* rpb_t   = (const float*)d_in[5];
    const float* proj_w  = (const float*)d_in[6];
    const float* proj_b  = (const float*)d_in[7];
    const float* norm2_g = (const float*)d_in[8];
    const float* norm2_b = (const float*)d_in[9];
    const float* fc1_w   = (const float*)d_in[10];
    const float* fc1_b   = (const float*)d_in[11];
    const float* fc2_w   = (const float*)d_in[12];
    const float* fc2_b   = (const float*)d_in[13];
    float* out = (float*)d_out;

    float *xw, *qkvbuf, *ao, *proj, *x1, *hbuf;
    cudaGetSymbolAddress((void**)&xw,     g_xw);
    cudaGetSymbolAddress((void**)&qkvbuf, g_qkv);
    cudaGetSymbolAddress((void**)&ao,     g_ao);
    cudaGetSymbolAddress((void**)&proj,   g_proj);
    cudaGetSymbolAddress((void**)&x1,     g_x1);
    cudaGetSymbolAddress((void**)&hbuf,   g_h);

    const int lnGrid = (NROWS + 7) / 8;

    // 1. LN1 + shift + window partition
    ln_kernel<<<lnGrid, 256>>>(x, norm1_g, norm1_b, xw, 1);

    // 2. QKV GEMM [100352,192] @ [192,576]
    mma_gemm<0><<<dim3(QKVDIM / 64, NROWS / 128), 256>>>(
        xw, qkv_w, qkv_b, qkvbuf, nullptr, NROWS, QKVDIM, CDIM);

    // 3. Windowed attention
    attn_kernel<<<32 * NWIN * NHEAD, 256>>>(qkvbuf, rpb_t, ao);

    // 4. Projection GEMM [100352,192] @ [192,192]
    mma_gemm<0><<<dim3(CDIM / 64, NROWS / 128), 256>>>(
        ao, proj_w, proj_b, proj, nullptr, NROWS, CDIM, CDIM);

    // 5. Un-window + un-shift + residual
    scatter_add_kernel<<<(NROWS * 48 + 255) / 256, 256>>>(proj, x, x1);

    // 6. LN2
    ln_kernel<<<lnGrid, 256>>>(x1, norm2_g, norm2_b, xw, 0);

    // 7. FC1 + exact GELU [100352,192] @ [192,768]
    mma_gemm<1><<<dim3(HID / 64, NROWS / 128), 256>>>(
        xw, fc1_w, fc1_b, hbuf, nullptr, NROWS, HID, CDIM);

    // 8. FC2 + residual [100352,768] @ [768,192] -> d_out
    mma_gemm<2><<<dim3(CDIM / 64, NROWS / 128), 256>>>(
        hbuf, fc2_w, fc2_b, out, x1, NROWS, CDIM, HID);
}

// round 4
// speedup vs baseline: 2.1951x; 1.1067x over previous
#include <cuda_runtime.h>
#include <math.h>
#include <stdint.h>

// Problem constants
#define NROWS   100352          // B*H*W = B*nW*N = 32*56*56
#define CDIM    192
#define HID     768
#define QKVDIM  576
#define NHEAD   6
#define HDIM    32
#define NTOK    49
#define NWIN    64

// -------- scratch (device globals; no allocation allowed) --------
__device__ float g_xw  [(size_t)NROWS * CDIM];
__device__ float g_qkv [(size_t)NROWS * QKVDIM];
__device__ float g_ao  [(size_t)NROWS * CDIM];
__device__ float g_x1  [(size_t)NROWS * CDIM];
__device__ float g_h   [(size_t)NROWS * HID];

// ---------------------------------------------------------------
// LayerNorm (mode 1: shift+window gather for ln1; mode 0: identity)
// ---------------------------------------------------------------
__global__ void ln_kernel(const float* __restrict__ x,
                          const float* __restrict__ gw,
                          const float* __restrict__ gb,
                          float* __restrict__ out, int mode)
{
    int warp = (blockIdx.x * blockDim.x + threadIdx.x) >> 5;
    int lane = threadIdx.x & 31;
    if (warp >= NROWS) return;

    const float* src;
    if (mode == 1) {
        int bb  = warp / 3136;
        int rem = warp % 3136;
        int win = rem / NTOK;
        int n   = rem % NTOK;
        int h_s = (win >> 3) * 7 + n / 7;
        int w_s = (win & 7) * 7 + n % 7;
        int hh = (h_s + 3) % 56;
        int ww = (w_s + 3) % 56;
        src = x + ((size_t)bb * 3136 + hh * 56 + ww) * CDIM;
    } else {
        src = x + (size_t)warp * CDIM;
    }

    float v[6];
    float s = 0.f, sq = 0.f;
    #pragma unroll
    for (int k = 0; k < 6; k++) {
        v[k] = src[lane + 32 * k];
        s += v[k];
        sq += v[k] * v[k];
    }
    #pragma unroll
    for (int o = 16; o; o >>= 1) {
        s  += __shfl_xor_sync(0xFFFFFFFFu, s, o);
        sq += __shfl_xor_sync(0xFFFFFFFFu, sq, o);
    }
    float mu  = s * (1.f / 192.f);
    float var = sq * (1.f / 192.f) - mu * mu;
    float rs  = rsqrtf(var + 1e-5f);

    float* dst = out + (size_t)warp * CDIM;
    #pragma unroll
    for (int k = 0; k < 6; k++) {
        int c = lane + 32 * k;
        dst[c] = (v[k] - mu) * rs * gw[c] + gb[c];
    }
}

// ---------------------------------------------------------------
// TF32 tensor-core GEMM. BM=128, BN=64, BK=16, 3-stage cp.async,
// SINGLE sync per K-tile (issue-after-sync ordering).
// EPI: 0 none, 1 exact GELU, 2 residual add (same layout),
//      3 scatter residual: C[image(row)] = acc + res[image(row)]
// ---------------------------------------------------------------
#define AS_STRIDE 20
#define BS_STRIDE 72
#define A_F       (128 * AS_STRIDE)
#define B_F       (16 * BS_STRIDE)
#define STAGE_F   (A_F + B_F)
#define STAGES    3

__device__ __forceinline__ void cp16(uint32_t dst, const void* src) {
    asm volatile("cp.async.cg.shared.global [%0], [%1], 16;" :: "r"(dst), "l"(src));
}
__device__ __forceinline__ void cp_commit() {
    asm volatile("cp.async.commit_group;");
}
__device__ __forceinline__ void cp_wait1() {
    asm volatile("cp.async.wait_group 1;" ::: "memory");
}

__device__ __forceinline__ void mma_tf32(float d[4], const uint32_t a[4], const uint32_t b[2]) {
    asm volatile(
        "mma.sync.aligned.m16n8k8.row.col.f32.tf32.tf32.f32 "
        "{%0,%1,%2,%3}, {%4,%5,%6,%7}, {%8,%9}, {%0,%1,%2,%3};\n"
        : "+f"(d[0]), "+f"(d[1]), "+f"(d[2]), "+f"(d[3])
        : "r"(a[0]), "r"(a[1]), "r"(a[2]), "r"(a[3]), "r"(b[0]), "r"(b[1]));
}

template <int EPI>
__global__ void __launch_bounds__(256)
mma_gemm(const float* __restrict__ A,
         const float* __restrict__ W,
         const float* __restrict__ bias,
         float* __restrict__ C,
         const float* __restrict__ res,
         int M, int N, int K)
{
    __shared__ float sm[STAGES * STAGE_F];

    const int t    = threadIdx.x;
    const int bm   = blockIdx.y * 128;
    const int bn   = blockIdx.x * 64;
    const int lane = t & 31;
    const int w    = t >> 5;
    const int g    = lane >> 2;
    const int tig  = lane & 3;
    const int wm   = (w & 3) * 32;
    const int wn   = (w >> 2) * 32;

    const int arow = t >> 2;
    const int ac   = (t & 3) * 4;
    const int brow = t >> 4;
    const int bc   = (t & 15) * 4;

    float acc[2][4][4] = {};

    auto issue = [&](int stage, int kt) {
        float* As = sm + stage * STAGE_F;
        float* Bs = As + A_F;
        const float* ag = A + (size_t)(bm + arow) * K + kt * 16 + ac;
        uint32_t ad = (uint32_t)__cvta_generic_to_shared(As + arow * AS_STRIDE + ac);
        cp16(ad, ag);
        cp16(ad + 64 * AS_STRIDE * 4, ag + (size_t)64 * K);
        const float* wg = W + (size_t)(kt * 16 + brow) * N + bn + bc;
        cp16((uint32_t)__cvta_generic_to_shared(Bs + brow * BS_STRIDE + bc), wg);
    };

    auto compute = [&](int stage) {
        const float* As = sm + stage * STAGE_F;
        const float* Bs = As + A_F;
        #pragma unroll
        for (int ks = 0; ks < 16; ks += 8) {
            uint32_t a[2][4], b[4][2];
            #pragma unroll
            for (int mi = 0; mi < 2; mi++) {
                const float* ap = As + (wm + mi * 16) * AS_STRIDE + ks;
                a[mi][0] = __float_as_uint(ap[g * AS_STRIDE + tig]);
                a[mi][1] = __float_as_uint(ap[(g + 8) * AS_STRIDE + tig]);
                a[mi][2] = __float_as_uint(ap[g * AS_STRIDE + tig + 4]);
                a[mi][3] = __float_as_uint(ap[(g + 8) * AS_STRIDE + tig + 4]);
            }
            #pragma unroll
            for (int ni = 0; ni < 4; ni++) {
                const float* bp = Bs + (ks + tig) * BS_STRIDE + wn + ni * 8 + g;
                b[ni][0] = __float_as_uint(bp[0]);
                b[ni][1] = __float_as_uint(bp[4 * BS_STRIDE]);
            }
            #pragma unroll
            for (int mi = 0; mi < 2; mi++)
                #pragma unroll
                for (int ni = 0; ni < 4; ni++)
                    mma_tf32(acc[mi][ni], a[mi], b[ni]);
        }
    };

    const int KT = K >> 4;
    issue(0, 0); cp_commit();
    issue(1, 1); cp_commit();

    // single-sync multistage mainloop
    for (int kt = 0; kt < KT; kt++) {
        cp_wait1();                 // stage kt landed
        __syncthreads();            // everyone done reading stage (kt+2)%3
        if (kt + 2 < KT) issue((kt + 2) % 3, kt + 2);
        cp_commit();
        compute(kt % 3);
    }

    // Epilogue
    float2 bia[4];
    #pragma unroll
    for (int ni = 0; ni < 4; ni++)
        bia[ni] = *(const float2*)(bias + bn + wn + ni * 8 + tig * 2);

    #pragma unroll
    for (int mi = 0; mi < 2; mi++) {
        #pragma unroll
        for (int half = 0; half < 2; half++) {
            int row = bm + wm + mi * 16 + g + half * 8;
            size_t rowoff;
            if (EPI == 3) {
                int bb  = row / 3136;
                int rem = row % 3136;
                int win = rem / NTOK;
                int n   = rem % NTOK;
                int h_s = (win >> 3) * 7 + n / 7;
                int w_s = (win & 7) * 7 + n % 7;
                int hh = (h_s + 3) % 56;
                int ww = (w_s + 3) % 56;
                rowoff = ((size_t)bb * 3136 + hh * 56 + ww) * CDIM;
            } else {
                rowoff = (size_t)row * N;
            }
            #pragma unroll
            for (int ni = 0; ni < 4; ni++) {
                int col = bn + wn + ni * 8 + tig * 2;
                float v0 = acc[mi][ni][half * 2 + 0] + bia[ni].x;
                float v1 = acc[mi][ni][half * 2 + 1] + bia[ni].y;
                if (EPI == 1) {
                    v0 = 0.5f * v0 * (1.f + erff(v0 * 0.70710678118654752f));
                    v1 = 0.5f * v1 * (1.f + erff(v1 * 0.70710678118654752f));
                }
                size_t o = rowoff + col;
                if (EPI == 2 || EPI == 3) {
                    float2 r = *(const float2*)(res + o);
                    v0 += r.x; v1 += r.y;
                }
                *(float2*)(C + o) = make_float2(v0, v1);
            }
        }
    }
}

// ---------------------------------------------------------------
// Windowed attention, vectorized. One block per (batch, window, head).
// q/k/v tiles stride 36 floats (float4-aligned, bank-clean).
// ---------------------------------------------------------------
#define QSTR 36
__global__ void __launch_bounds__(256)
attn_kernel(const float* __restrict__ qkv,
            const float* __restrict__ rpb_table,
            float* __restrict__ ao)
{
    __shared__ float qs[NTOK * QSTR];
    __shared__ float ks[NTOK * QSTR];
    __shared__ float vs[NTOK * QSTR];
    __shared__ float sc[NTOK][NTOK + 1];

    const int bid  = blockIdx.x;
    const int head = bid % NHEAD;
    const int win  = (bid / NHEAD) % NWIN;
    const int bb   = bid / (NHEAD * NWIN);
    const int tid  = threadIdx.x;

    const size_t baserow = (size_t)(bb * NWIN + win) * NTOK;

    // Load q/k/v (float4): 49*8 = 392 vec4 per tensor
    for (int idx = tid; idx < NTOK * 8; idx += 256) {
        int n = idx >> 3, d4 = idx & 7;
        const float* p = qkv + (baserow + n) * QKVDIM + head * HDIM + d4 * 4;
        *(float4*)(qs + n * QSTR + d4 * 4) = *(const float4*)(p);
        *(float4*)(ks + n * QSTR + d4 * 4) = *(const float4*)(p + CDIM);
        *(float4*)(vs + n * QSTR + d4 * 4) = *(const float4*)(p + 2 * CDIM);
    }
    __syncthreads();

    const int wh = win >> 3, ww = win & 7;
    const float scale = 0.17677669529663687f;

    // Scores: float4 dot products
    for (int idx = tid; idx < NTOK * NTOK; idx += 256) {
        int i = idx / NTOK, j = idx % NTOK;
        const float4* q4 = (const float4*)(qs + i * QSTR);
        const float4* k4 = (const float4*)(ks + j * QSTR);
        float s = 0.f;
        #pragma unroll
        for (int d = 0; d < 8; d++) {
            float4 a = q4[d], b = k4[d];
            s += a.x * b.x + a.y * b.y + a.z * b.z + a.w * b.w;
        }
        s *= scale;

        int ih = i / 7, iw = i % 7, jh = j / 7, jw = j % 7;
        s += rpb_table[((ih - jh + 6) * 13 + (iw - jw + 6)) * NHEAD + head];

        int hi = wh * 7 + ih, wi = ww * 7 + iw;
        int hj = wh * 7 + jh, wj = ww * 7 + jw;
        int ri = (hi < 49 ? 0 : (hi < 53 ? 1 : 2)) * 3 + (wi < 49 ? 0 : (wi < 53 ? 1 : 2));
        int rj = (hj < 49 ? 0 : (hj < 53 ? 1 : 2)) * 3 + (wj < 49 ? 0 : (wj < 53 ? 1 : 2));
        if (ri != rj) s -= 100.f;

        sc[i][j] = s;
    }
    __syncthreads();

    // Softmax: one warp per row
    int warp = tid >> 5, lane = tid & 31;
    for (int i = warp; i < NTOK; i += 8) {
        float m = -1e30f;
        for (int j = lane; j < NTOK; j += 32) m = fmaxf(m, sc[i][j]);
        #pragma unroll
        for (int o = 16; o; o >>= 1) m = fmaxf(m, __shfl_xor_sync(0xFFFFFFFFu, m, o));
        float sum = 0.f;
        for (int j = lane; j < NTOK; j += 32) {
            float e = expf(sc[i][j] - m);
            sc[i][j] = e;
            sum += e;
        }
        #pragma unroll
        for (int o = 16; o; o >>= 1) sum += __shfl_xor_sync(0xFFFFFFFFu, sum, o);
        float inv = 1.f / sum;
        for (int j = lane; j < NTOK; j += 32) sc[i][j] *= inv;
    }
    __syncthreads();

    // out = attn @ v : each thread computes 4 outputs (i, d4)
    for (int idx = tid; idx < NTOK * 8; idx += 256) {
        int i = idx >> 3, d4 = idx & 7;
        float4 o = make_float4(0.f, 0.f, 0.f, 0.f);
        const float* sci = sc[i];
        #pragma unroll 7
        for (int j = 0; j < NTOK; j++) {
            float wv = sci[j];
            float4 v = *(const float4*)(vs + j * QSTR + d4 * 4);
            o.x += wv * v.x; o.y += wv * v.y; o.z += wv * v.z; o.w += wv * v.w;
        }
        *(float4*)(ao + (baserow + i) * CDIM + head * HDIM + d4 * 4) = o;
    }
}

// ---------------------------------------------------------------
extern "C" void kernel_launch(void* const* d_in, const int* in_sizes, int n_in,
                              void* d_out, int out_size)
{
    const float* x       = (const float*)d_in[0];
    const float* norm1_g = (const float*)d_in[1];
    const float* norm1_b = (const float*)d_in[2];
    const float* qkv_w   = (const float*)d_in[3];
    const float* qkv_b   = (const float*)d_in[4];
    const float* rpb_t   = (const float*)d_in[5];
    const float* proj_w  = (const float*)d_in[6];
    const float* proj_b  = (const float*)d_in[7];
    const float* norm2_g = (const float*)d_in[8];
    const float* norm2_b = (const float*)d_in[9];
    const float* fc1_w   = (const float*)d_in[10];
    const float* fc1_b   = (const float*)d_in[11];
    const float* fc2_w   = (const float*)d_in[12];
    const float* fc2_b   = (const float*)d_in[13];
    float* out = (float*)d_out;

    float *xw, *qkvbuf, *ao, *x1, *hbuf;
    cudaGetSymbolAddress((void**)&xw,     g_xw);
    cudaGetSymbolAddress((void**)&qkvbuf, g_qkv);
    cudaGetSymbolAddress((void**)&ao,     g_ao);
    cudaGetSymbolAddress((void**)&x1,     g_x1);
    cudaGetSymbolAddress((void**)&hbuf,   g_h);

    const int lnGrid = (NROWS + 7) / 8;

    // 1. LN1 + shift + window partition
    ln_kernel<<<lnGrid, 256>>>(x, norm1_g, norm1_b, xw, 1);

    // 2. QKV GEMM [100352,192] @ [192,576]
    mma_gemm<0><<<dim3(QKVDIM / 64, NROWS / 128), 256>>>(
        xw, qkv_w, qkv_b, qkvbuf, nullptr, NROWS, QKVDIM, CDIM);

    // 3. Windowed attention
    attn_kernel<<<32 * NWIN * NHEAD, 256>>>(qkvbuf, rpb_t, ao);

    // 4. Projection GEMM + fused un-shift/un-window + residual -> x1 (image layout)
    mma_gemm<3><<<dim3(CDIM / 64, NROWS / 128), 256>>>(
        ao, proj_w, proj_b, x1, x, NROWS, CDIM, CDIM);

    // 5. LN2
    ln_kernel<<<lnGrid, 256>>>(x1, norm2_g, norm2_b, xw, 0);

    // 6. FC1 + exact GELU [100352,192] @ [192,768]
    mma_gemm<1><<<dim3(HID / 64, NROWS / 128), 256>>>(
        xw, fc1_w, fc1_b, hbuf, nullptr, NROWS, HID, CDIM);

    // 7. FC2 + residual [100352,768] @ [768,192] -> d_out
    mma_gemm<2><<<dim3(CDIM / 64, NROWS / 128), 256>>>(
        hbuf, fc2_w, fc2_b, out, x1, NROWS, CDIM, HID);
}

// round 8
// speedup vs baseline: 2.3169x; 1.0555x over previous
#include <cuda_runtime.h>
#include <math.h>
#include <stdint.h>

// Problem constants
#define NROWS   100352          // B*H*W = 32*56*56
#define CDIM    192
#define HID     768
#define QKVDIM  576
#define NHEAD   6
#define HDIM    32
#define NTOK    49
#define NWIN    64

// -------- scratch (device globals) --------
__device__ float g_xw  [(size_t)NROWS * CDIM];
__device__ float g_qkv [(size_t)NROWS * QKVDIM];
__device__ float g_ao  [(size_t)NROWS * CDIM];
__device__ float g_x1  [(size_t)NROWS * CDIM];
__device__ float g_h   [(size_t)NROWS * HID];
// transposed weights [N][K] K-major
__device__ float g_wt_qkv [QKVDIM * CDIM];
__device__ float g_wt_proj[CDIM * CDIM];
__device__ float g_wt_fc1 [HID * CDIM];
__device__ float g_wt_fc2 [CDIM * HID];

// ================================================================
// PTX helpers (portable sm_100 set: cp.async / ldmatrix / mma.sync)
// ================================================================
__device__ __forceinline__ void cp16(uint32_t dst, const void* src) {
    asm volatile("cp.async.cg.shared.global [%0], [%1], 16;" :: "r"(dst), "l"(src));
}
__device__ __forceinline__ void cp_commit() {
    asm volatile("cp.async.commit_group;");
}
__device__ __forceinline__ void cp_wait1() {
    asm volatile("cp.async.wait_group 1;" ::: "memory");
}
__device__ __forceinline__ void ldm_x4(uint32_t r[4], uint32_t addr) {
    asm volatile("ldmatrix.sync.aligned.m8n8.x4.shared.b16 {%0,%1,%2,%3}, [%4];"
                 : "=r"(r[0]), "=r"(r[1]), "=r"(r[2]), "=r"(r[3]) : "r"(addr));
}
__device__ __forceinline__ void mma_tf32(float d[4], const uint32_t a[4], const uint32_t b[2]) {
    asm volatile(
        "mma.sync.aligned.m16n8k8.row.col.f32.tf32.tf32.f32 "
        "{%0,%1,%2,%3}, {%4,%5,%6,%7}, {%8,%9}, {%0,%1,%2,%3};\n"
        : "+f"(d[0]), "+f"(d[1]), "+f"(d[2]), "+f"(d[3])
        : "r"(a[0]), "r"(a[1]), "r"(a[2]), "r"(a[3]), "r"(b[0]), "r"(b[1]));
}

// ================================================================
// Weight transpose: out[n*K + k] = in[k*N + n]
// ================================================================
__global__ void transpose_kernel(const float* __restrict__ in, float* __restrict__ out,
                                 int K, int N)
{
    int idx = blockIdx.x * 256 + threadIdx.x;
    if (idx >= K * N) return;
    int k = idx / N, n = idx % N;
    out[(size_t)n * K + k] = in[idx];
}

// ================================================================
// TF32 tensor-core GEMM with ldmatrix fragment loads.
// C[M,N] = A[M,K] @ WT[N,K]^T + bias (+epilogue)
// BM=128, BN=64, BK=16, 3-stage cp.async, 128 threads (4 warps),
// warp tile 64x32 (2M x 2N warps), mma.m16n8k8.tf32.
// A smem [m][k] stride 20; B smem [n][k] stride 20 (both ldmatrix-clean).
// EPI: 0 none, 1 exact GELU, 2 residual add, 3 scatter residual.
// ================================================================
#define AS_STR  20
#define BS_STR  20
#define A_F     (128 * AS_STR)      // 2560 floats
#define B_F     (64 * BS_STR)       // 1280 floats
#define STAGE_F (A_F + B_F)         // 3840 floats (15 KB)
#define STAGES  3

template <int EPI>
__global__ void __launch_bounds__(128)
mma_gemm(const float* __restrict__ A,
         const float* __restrict__ WT,
         const float* __restrict__ bias,
         float* __restrict__ C,
         const float* __restrict__ res,
         int M, int N, int K)
{
    __shared__ __align__(16) float sm[STAGES * STAGE_F];

    const int t    = threadIdx.x;
    const int bm   = blockIdx.y * 128;
    const int bn   = blockIdx.x * 64;
    const int lane = t & 31;
    const int w    = t >> 5;
    const int g    = lane >> 2;          // 0..7
    const int tig  = lane & 3;           // 0..3
    const int q    = lane >> 3;          // ldmatrix tile id 0..3
    const int r8   = lane & 7;           // ldmatrix row in tile
    const int wm   = (w & 1) * 64;
    const int wn   = (w >> 1) * 32;

    float acc[4][4][4] = {};

    auto issue = [&](int stage, int kt) {
        float* As = sm + stage * STAGE_F;
        float* Bs = As + A_F;
        #pragma unroll
        for (int i = 0; i < 4; i++) {
            int f   = t + i * 128;       // 0..511
            int row = f >> 2;
            int c4  = (f & 3) * 4;
            cp16((uint32_t)__cvta_generic_to_shared(As + row * AS_STR + c4),
                 A + (size_t)(bm + row) * K + kt * 16 + c4);
        }
        #pragma unroll
        for (int i = 0; i < 2; i++) {
            int f   = t + i * 128;       // 0..255
            int row = f >> 2;
            int c4  = (f & 3) * 4;
            cp16((uint32_t)__cvta_generic_to_shared(Bs + row * BS_STR + c4),
                 WT + (size_t)(bn + row) * K + kt * 16 + c4);
        }
    };

    auto compute = [&](int stage) {
        const float* As = sm + stage * STAGE_F;
        const float* Bs = As + A_F;
        #pragma unroll
        for (int ks = 0; ks < 16; ks += 8) {
            uint32_t a[4][4];
            uint32_t b[4][2];
            #pragma unroll
            for (int mb = 0; mb < 4; mb++) {
                uint32_t addr = (uint32_t)__cvta_generic_to_shared(
                    As + (wm + mb * 16 + (q & 1) * 8 + r8) * AS_STR + ks + (q >> 1) * 4);
                ldm_x4(a[mb], addr);
            }
            #pragma unroll
            for (int nb2 = 0; nb2 < 2; nb2++) {
                uint32_t bt[4];
                uint32_t addr = (uint32_t)__cvta_generic_to_shared(
                    Bs + (wn + nb2 * 16 + (q >> 1) * 8 + r8) * BS_STR + ks + (q & 1) * 4);
                ldm_x4(bt, addr);
                b[nb2 * 2 + 0][0] = bt[0]; b[nb2 * 2 + 0][1] = bt[1];
                b[nb2 * 2 + 1][0] = bt[2]; b[nb2 * 2 + 1][1] = bt[3];
            }
            #pragma unroll
            for (int mi = 0; mi < 4; mi++)
                #pragma unroll
                for (int ni = 0; ni < 4; ni++)
                    mma_tf32(acc[mi][ni], a[mi], b[ni]);
        }
    };

    const int KT = K >> 4;
    issue(0, 0); cp_commit();
    issue(1, 1); cp_commit();

    for (int kt = 0; kt < KT; kt++) {
        cp_wait1();
        __syncthreads();
        if (kt + 2 < KT) issue((kt + 2) % 3, kt + 2);
        cp_commit();
        compute(kt % 3);
    }

    // ---- epilogue ----
    float2 bia[4];
    #pragma unroll
    for (int ni = 0; ni < 4; ni++)
        bia[ni] = *(const float2*)(bias + bn + wn + ni * 8 + tig * 2);

    #pragma unroll
    for (int mi = 0; mi < 4; mi++) {
        #pragma unroll
        for (int half = 0; half < 2; half++) {
            int row = bm + wm + mi * 16 + g + half * 8;
            size_t rowoff;
            if (EPI == 3) {
                int bb  = row / 3136;
                int rem = row % 3136;
                int win = rem / NTOK;
                int n   = rem % NTOK;
                int h_s = (win >> 3) * 7 + n / 7;
                int w_s = (win & 7) * 7 + n % 7;
                int hh = (h_s + 3) % 56;
                int ww = (w_s + 3) % 56;
                rowoff = ((size_t)bb * 3136 + hh * 56 + ww) * CDIM;
            } else {
                rowoff = (size_t)row * N;
            }
            #pragma unroll
            for (int ni = 0; ni < 4; ni++) {
                int col = bn + wn + ni * 8 + tig * 2;
                float v0 = acc[mi][ni][half * 2 + 0] + bia[ni].x;
                float v1 = acc[mi][ni][half * 2 + 1] + bia[ni].y;
                if (EPI == 1) {
                    v0 = 0.5f * v0 * (1.f + erff(v0 * 0.70710678118654752f));
                    v1 = 0.5f * v1 * (1.f + erff(v1 * 0.70710678118654752f));
                }
                size_t o = rowoff + col;
                if (EPI == 2 || EPI == 3) {
                    float2 rr = *(const float2*)(res + o);
                    v0 += rr.x; v1 += rr.y;
                }
                *(float2*)(C + o) = make_float2(v0, v1);
            }
        }
    }
}

// ================================================================
// LayerNorm (mode 1: shift+window gather for ln1; mode 0: identity)
// ================================================================
__global__ void ln_kernel(const float* __restrict__ x,
                          const float* __restrict__ gw,
                          const float* __restrict__ gb,
                          float* __restrict__ out, int mode)
{
    int warp = (blockIdx.x * blockDim.x + threadIdx.x) >> 5;
    int lane = threadIdx.x & 31;
    if (warp >= NROWS) return;

    const float* src;
    if (mode == 1) {
        int bb  = warp / 3136;
        int rem = warp % 3136;
        int win = rem / NTOK;
        int n   = rem % NTOK;
        int h_s = (win >> 3) * 7 + n / 7;
        int w_s = (win & 7) * 7 + n % 7;
        int hh = (h_s + 3) % 56;
        int ww = (w_s + 3) % 56;
        src = x + ((size_t)bb * 3136 + hh * 56 + ww) * CDIM;
    } else {
        src = x + (size_t)warp * CDIM;
    }

    float v[6];
    float s = 0.f, sq = 0.f;
    #pragma unroll
    for (int k = 0; k < 6; k++) {
        v[k] = src[lane + 32 * k];
        s += v[k];
        sq += v[k] * v[k];
    }
    #pragma unroll
    for (int o = 16; o; o >>= 1) {
        s  += __shfl_xor_sync(0xFFFFFFFFu, s, o);
        sq += __shfl_xor_sync(0xFFFFFFFFu, sq, o);
    }
    float mu  = s * (1.f / 192.f);
    float var = sq * (1.f / 192.f) - mu * mu;
    float rs  = rsqrtf(var + 1e-5f);

    float* dst = out + (size_t)warp * CDIM;
    #pragma unroll
    for (int k = 0; k < 6; k++) {
        int c = lane + 32 * k;
        dst[c] = (v[k] - mu) * rs * gw[c] + gb[c];
    }
}

// ================================================================
// Windowed attention (vectorized)
// ================================================================
#define QSTR 36
__global__ void __launch_bounds__(256)
attn_kernel(const float* __restrict__ qkv,
            const float* __restrict__ rpb_table,
            float* __restrict__ ao)
{
    __shared__ __align__(16) float qs[NTOK * QSTR];
    __shared__ __align__(16) float ks[NTOK * QSTR];
    __shared__ __align__(16) float vs[NTOK * QSTR];
    __shared__ float sc[NTOK][NTOK + 1];

    const int bid  = blockIdx.x;
    const int head = bid % NHEAD;
    const int win  = (bid / NHEAD) % NWIN;
    const int bb   = bid / (NHEAD * NWIN);
    const int tid  = threadIdx.x;

    const size_t baserow = (size_t)(bb * NWIN + win) * NTOK;

    for (int idx = tid; idx < NTOK * 8; idx += 256) {
        int n = idx >> 3, d4 = idx & 7;
        const float* p = qkv + (baserow + n) * QKVDIM + head * HDIM + d4 * 4;
        *(float4*)(qs + n * QSTR + d4 * 4) = *(const float4*)(p);
        *(float4*)(ks + n * QSTR + d4 * 4) = *(const float4*)(p + CDIM);
        *(float4*)(vs + n * QSTR + d4 * 4) = *(const float4*)(p + 2 * CDIM);
    }
    __syncthreads();

    const int wh = win >> 3, ww = win & 7;
    const float scale = 0.17677669529663687f;

    for (int idx = tid; idx < NTOK * NTOK; idx += 256) {
        int i = idx / NTOK, j = idx % NTOK;
        const float4* q4 = (const float4*)(qs + i * QSTR);
        const float4* k4 = (const float4*)(ks + j * QSTR);
        float s = 0.f;
        #pragma unroll
        for (int d = 0; d < 8; d++) {
            float4 a = q4[d], b = k4[d];
            s += a.x * b.x + a.y * b.y + a.z * b.z + a.w * b.w;
        }
        s *= scale;

        int ih = i / 7, iw = i % 7, jh = j / 7, jw = j % 7;
        s += rpb_table[((ih - jh + 6) * 13 + (iw - jw + 6)) * NHEAD + head];

        int hi = wh * 7 + ih, wi = ww * 7 + iw;
        int hj = wh * 7 + jh, wj = ww * 7 + jw;
        int ri = (hi < 49 ? 0 : (hi < 53 ? 1 : 2)) * 3 + (wi < 49 ? 0 : (wi < 53 ? 1 : 2));
        int rj = (hj < 49 ? 0 : (hj < 53 ? 1 : 2)) * 3 + (wj < 49 ? 0 : (wj < 53 ? 1 : 2));
        if (ri != rj) s -= 100.f;

        sc[i][j] = s;
    }
    __syncthreads();

    int warp = tid >> 5, lane = tid & 31;
    for (int i = warp; i < NTOK; i += 8) {
        float m = -1e30f;
        for (int j = lane; j < NTOK; j += 32) m = fmaxf(m, sc[i][j]);
        #pragma unroll
        for (int o = 16; o; o >>= 1) m = fmaxf(m, __shfl_xor_sync(0xFFFFFFFFu, m, o));
        float sum = 0.f;
        for (int j = lane; j < NTOK; j += 32) {
            float e = expf(sc[i][j] - m);
            sc[i][j] = e;
            sum += e;
        }
        #pragma unroll
        for (int o = 16; o; o >>= 1) sum += __shfl_xor_sync(0xFFFFFFFFu, sum, o);
        float inv = 1.f / sum;
        for (int j = lane; j < NTOK; j += 32) sc[i][j] *= inv;
    }
    __syncthreads();

    for (int idx = tid; idx < NTOK * 8; idx += 256) {
        int i = idx >> 3, d4 = idx & 7;
        float4 o = make_float4(0.f, 0.f, 0.f, 0.f);
        const float* sci = sc[i];
        #pragma unroll 7
        for (int j = 0; j < NTOK; j++) {
            float wv = sci[j];
            float4 v = *(const float4*)(vs + j * QSTR + d4 * 4);
            o.x += wv * v.x; o.y += wv * v.y; o.z += wv * v.z; o.w += wv * v.w;
        }
        *(float4*)(ao + (baserow + i) * CDIM + head * HDIM + d4 * 4) = o;
    }
}

// ================================================================
extern "C" void kernel_launch(void* const* d_in, const int* in_sizes, int n_in,
                              void* d_out, int out_size)
{
    const float* x       = (const float*)d_in[0];
    const float* norm1_g = (const float*)d_in[1];
    const float* norm1_b = (const float*)d_in[2];
    const float* qkv_w   = (const float*)d_in[3];
    const float* qkv_b   = (const float*)d_in[4];
    const float* rpb_t   = (const float*)d_in[5];
    const float* proj_w  = (const float*)d_in[6];
    const float* proj_b  = (const float*)d_in[7];
    const float* norm2_g = (const float*)d_in[8];
    const float* norm2_b = (const float*)d_in[9];
    const float* fc1_w   = (const float*)d_in[10];
    const float* fc1_b   = (const float*)d_in[11];
    const float* fc2_w   = (const float*)d_in[12];
    const float* fc2_b   = (const float*)d_in[13];
    float* out = (float*)d_out;

    float *xw, *qkvbuf, *ao, *x1, *hbuf;
    float *wt_qkv, *wt_proj, *wt_fc1, *wt_fc2;
    cudaGetSymbolAddress((void**)&xw,      g_xw);
    cudaGetSymbolAddress((void**)&qkvbuf,  g_qkv);
    cudaGetSymbolAddress((void**)&ao,      g_ao);
    cudaGetSymbolAddress((void**)&x1,      g_x1);
    cudaGetSymbolAddress((void**)&hbuf,    g_h);
    cudaGetSymbolAddress((void**)&wt_qkv,  g_wt_qkv);
    cudaGetSymbolAddress((void**)&wt_proj, g_wt_proj);
    cudaGetSymbolAddress((void**)&wt_fc1,  g_wt_fc1);
    cudaGetSymbolAddress((void**)&wt_fc2,  g_wt_fc2);

    const int lnGrid = (NROWS + 7) / 8;

    // 0. Weight transposes -> [N][K] K-major
    transpose_kernel<<<(CDIM * QKVDIM + 255) / 256, 256>>>(qkv_w,  wt_qkv,  CDIM, QKVDIM);
    transpose_kernel<<<(CDIM * CDIM   + 255) / 256, 256>>>(proj_w, wt_proj, CDIM, CDIM);
    transpose_kernel<<<(CDIM * HID    + 255) / 256, 256>>>(fc1_w,  wt_fc1,  CDIM, HID);
    transpose_kernel<<<(HID  * CDIM   + 255) / 256, 256>>>(fc2_w,  wt_fc2,  HID,  CDIM);

    // 1. LN1 + shift + window partition
    ln_kernel<<<lnGrid, 256>>>(x, norm1_g, norm1_b, xw, 1);

    // 2. QKV GEMM [100352,192] @ [192,576]
    mma_gemm<0><<<dim3(QKVDIM / 64, NROWS / 128), 128>>>(
        xw, wt_qkv, qkv_b, qkvbuf, nullptr, NROWS, QKVDIM, CDIM);

    // 3. Windowed attention
    attn_kernel<<<32 * NWIN * NHEAD, 256>>>(qkvbuf, rpb_t, ao);

    // 4. Projection GEMM + fused un-shift/un-window + residual -> x1
    mma_gemm<3><<<dim3(CDIM / 64, NROWS / 128), 128>>>(
        ao, wt_proj, proj_b, x1, x, NROWS, CDIM, CDIM);

    // 5. LN2
    ln_kernel<<<lnGrid, 256>>>(x1, norm2_g, norm2_b, xw, 0);

    // 6. FC1 + exact GELU [100352,192] @ [192,768]
    mma_gemm<1><<<dim3(HID / 64, NROWS / 128), 128>>>(
        xw, wt_fc1, fc1_b, hbuf, nullptr, NROWS, HID, CDIM);

    // 7. FC2 + residual [100352,768] @ [768,192] -> d_out
    mma_gemm<2><<<dim3(CDIM / 64, NROWS / 128), 128>>>(
        hbuf, wt_fc2, fc2_b, out, x1, NROWS, CDIM, HID);
}

// round 9
// speedup vs baseline: 2.9622x; 1.2785x over previous
#include <cuda_runtime.h>
#include <cuda_fp16.h>
#include <math.h>
#include <stdint.h>

// Problem constants
#define NROWS   100352          // B*H*W = 32*56*56
#define CDIM    192
#define HID     768
#define QKVDIM  576
#define NHEAD   6
#define HDIM    32
#define NTOK    49
#define NWIN    64

// -------- scratch (device globals) --------
__device__ __half g_xw  [(size_t)NROWS * CDIM];     // LN outputs (f16)
__device__ float  g_qkv [(size_t)NROWS * QKVDIM];   // qkv (fp32, read by attention)
__device__ __half g_ao  [(size_t)NROWS * CDIM];     // attention out (f16)
__device__ float  g_x1  [(size_t)NROWS * CDIM];     // residual 1 (fp32)
__device__ __half g_h   [(size_t)NROWS * HID];      // MLP hidden (f16)
// transposed weights [N][K] K-major, f16
__device__ __half g_wt_qkv [QKVDIM * CDIM];
__device__ __half g_wt_proj[CDIM * CDIM];
__device__ __half g_wt_fc1 [HID * CDIM];
__device__ __half g_wt_fc2 [CDIM * HID];

// ================================================================
// PTX helpers
// ================================================================
__device__ __forceinline__ void cp16(uint32_t dst, const void* src) {
    asm volatile("cp.async.cg.shared.global [%0], [%1], 16;" :: "r"(dst), "l"(src));
}
__device__ __forceinline__ void cp_commit() {
    asm volatile("cp.async.commit_group;");
}
__device__ __forceinline__ void cp_wait1() {
    asm volatile("cp.async.wait_group 1;" ::: "memory");
}
__device__ __forceinline__ void ldm_x4(uint32_t r[4], uint32_t addr) {
    asm volatile("ldmatrix.sync.aligned.m8n8.x4.shared.b16 {%0,%1,%2,%3}, [%4];"
                 : "=r"(r[0]), "=r"(r[1]), "=r"(r[2]), "=r"(r[3]) : "r"(addr));
}
__device__ __forceinline__ void mma_f16(float d[4], const uint32_t a[4], const uint32_t b[2]) {
    asm volatile(
        "mma.sync.aligned.m16n8k16.row.col.f32.f16.f16.f32 "
        "{%0,%1,%2,%3}, {%4,%5,%6,%7}, {%8,%9}, {%0,%1,%2,%3};\n"
        : "+f"(d[0]), "+f"(d[1]), "+f"(d[2]), "+f"(d[3])
        : "r"(a[0]), "r"(a[1]), "r"(a[2]), "r"(a[3]), "r"(b[0]), "r"(b[1]));
}

// ================================================================
// Weight transpose + f16 convert: out[n*K + k] = (half)in[k*N + n]
// ================================================================
__global__ void transpose_kernel(const float* __restrict__ in, __half* __restrict__ out,
                                 int K, int N)
{
    int idx = blockIdx.x * 256 + threadIdx.x;
    if (idx >= K * N) return;
    int k = idx / N, n = idx % N;
    out[(size_t)n * K + k] = __float2half(in[idx]);
}

// ================================================================
// F16 tensor-core GEMM (fp32 accumulate), ldmatrix fragment loads.
// C[M,N] = A[M,K] @ WT[N,K]^T + bias (+epilogue)
// BM=128, BN=64, BK=32(half), 3-stage cp.async, 128 threads (4 warps),
// warp tile 64x32 (2M x 2N warps), mma.m16n8k16.f16.f32.
// A smem [m][k] half stride 40; B smem [n][k] half stride 40.
// EPI: 0 none->float, 1 GELU->half, 2 residual->float, 3 scatter residual->float
// ================================================================
#define AS_STR  40                  // halves (80 B rows; conflict-free, 16B aligned)
#define A_H     (128 * AS_STR)      // 5120 halves
#define B_H     (64 * AS_STR)       // 2560 halves
#define STAGE_H (A_H + B_H)         // 7680 halves (15360 B)
#define STAGES  3

template <int EPI>
__global__ void __launch_bounds__(128)
mma_gemm(const __half* __restrict__ A,
         const __half* __restrict__ WT,
         const float* __restrict__ bias,
         void* __restrict__ Cv,
         const float* __restrict__ res,
         int M, int N, int K)
{
    __shared__ __align__(16) __half sm[STAGES * STAGE_H];

    const int t    = threadIdx.x;
    const int bm   = blockIdx.y * 128;
    const int bn   = blockIdx.x * 64;
    const int lane = t & 31;
    const int w    = t >> 5;
    const int g    = lane >> 2;          // 0..7
    const int tig  = lane & 3;           // 0..3
    const int q    = lane >> 3;          // ldmatrix lane-group 0..3
    const int r8   = lane & 7;           // row within 8-row matrix
    const int wm   = (w & 1) * 64;
    const int wn   = (w >> 1) * 32;

    float acc[4][4][4] = {};

    auto issue = [&](int stage, int kt) {
        __half* As = sm + stage * STAGE_H;
        __half* Bs = As + A_H;
        #pragma unroll
        for (int i = 0; i < 4; i++) {            // A: 128 rows x 4 chunks(16B)
            int f   = t + i * 128;               // 0..511
            int row = f >> 2;
            int c8  = (f & 3) * 8;               // half offset
            cp16((uint32_t)__cvta_generic_to_shared(As + row * AS_STR + c8),
                 A + (size_t)(bm + row) * K + kt * 32 + c8);
        }
        #pragma unroll
        for (int i = 0; i < 2; i++) {            // B: 64 rows x 4 chunks
            int f   = t + i * 128;               // 0..255
            int row = f >> 2;
            int c8  = (f & 3) * 8;
            cp16((uint32_t)__cvta_generic_to_shared(Bs + row * AS_STR + c8),
                 WT + (size_t)(bn + row) * K + kt * 32 + c8);
        }
    };

    auto compute = [&](int stage) {
        const __half* As = sm + stage * STAGE_H;
        const __half* Bs = As + A_H;
        #pragma unroll
        for (int ks = 0; ks < 32; ks += 16) {    // 2 k16 steps per stage
            uint32_t a[4][4];
            uint32_t b[4][2];
            #pragma unroll
            for (int mb = 0; mb < 4; mb++) {
                // matrices: q0=(r8,ks+0) q1=(8+r8,ks+0) q2=(r8,ks+8) q3=(8+r8,ks+8)
                uint32_t addr = (uint32_t)__cvta_generic_to_shared(
                    As + (wm + mb * 16 + (q & 1) * 8 + r8) * AS_STR + ks + (q >> 1) * 8);
                ldm_x4(a[mb], addr);
            }
            #pragma unroll
            for (int nb2 = 0; nb2 < 2; nb2++) {
                // matrices: q0=(n r8,ks+0) q1=(n r8,ks+8) q2=(n 8+r8,ks+0) q3=(n 8+r8,ks+8)
                uint32_t bt[4];
                uint32_t addr = (uint32_t)__cvta_generic_to_shared(
                    Bs + (wn + nb2 * 16 + (q >> 1) * 8 + r8) * AS_STR + ks + (q & 1) * 8);
                ldm_x4(bt, addr);
                b[nb2 * 2 + 0][0] = bt[0]; b[nb2 * 2 + 0][1] = bt[1];
                b[nb2 * 2 + 1][0] = bt[2]; b[nb2 * 2 + 1][1] = bt[3];
            }
            #pragma unroll
            for (int mi = 0; mi < 4; mi++)
                #pragma unroll
                for (int ni = 0; ni < 4; ni++)
                    mma_f16(acc[mi][ni], a[mi], b[ni]);
        }
    };

    const int KT = K >> 5;                       // BK = 32 halves
    issue(0, 0); cp_commit();
    issue(1, 1); cp_commit();

    for (int kt = 0; kt < KT; kt++) {
        cp_wait1();
        __syncthreads();
        if (kt + 2 < KT) issue((kt + 2) % 3, kt + 2);
        cp_commit();
        compute(kt % 3);
    }

    // ---- epilogue ----
    float2 bia[4];
    #pragma unroll
    for (int ni = 0; ni < 4; ni++)
        bia[ni] = *(const float2*)(bias + bn + wn + ni * 8 + tig * 2);

    #pragma unroll
    for (int mi = 0; mi < 4; mi++) {
        #pragma unroll
        for (int half_ = 0; half_ < 2; half_++) {
            int row = bm + wm + mi * 16 + g + half_ * 8;
            size_t rowoff;
            if (EPI == 3) {
                int bb  = row / 3136;
                int rem = row % 3136;
                int win = rem / NTOK;
                int n   = rem % NTOK;
                int h_s = (win >> 3) * 7 + n / 7;
                int w_s = (win & 7) * 7 + n % 7;
                int hh = (h_s + 3) % 56;
                int ww = (w_s + 3) % 56;
                rowoff = ((size_t)bb * 3136 + hh * 56 + ww) * CDIM;
            } else {
                rowoff = (size_t)row * N;
            }
            #pragma unroll
            for (int ni = 0; ni < 4; ni++) {
                int col = bn + wn + ni * 8 + tig * 2;
                float v0 = acc[mi][ni][half_ * 2 + 0] + bia[ni].x;
                float v1 = acc[mi][ni][half_ * 2 + 1] + bia[ni].y;
                size_t o = rowoff + col;
                if (EPI == 1) {
                    v0 = 0.5f * v0 * (1.f + erff(v0 * 0.70710678118654752f));
                    v1 = 0.5f * v1 * (1.f + erff(v1 * 0.70710678118654752f));
                    *(__half2*)((__half*)Cv + o) = __floats2half2_rn(v0, v1);
                } else {
                    if (EPI == 2 || EPI == 3) {
                        float2 rr = *(const float2*)(res + o);
                        v0 += rr.x; v1 += rr.y;
                    }
                    *(float2*)((float*)Cv + o) = make_float2(v0, v1);
                }
            }
        }
    }
}

// ================================================================
// LayerNorm (mode 1: shift+window gather for ln1; mode 0: identity)
// fp32 in -> f16 out
// ================================================================
__global__ void ln_kernel(const float* __restrict__ x,
                          const float* __restrict__ gw,
                          const float* __restrict__ gb,
                          __half* __restrict__ out, int mode)
{
    int warp = (blockIdx.x * blockDim.x + threadIdx.x) >> 5;
    int lane = threadIdx.x & 31;
    if (warp >= NROWS) return;

    const float* src;
    if (mode == 1) {
        int bb  = warp / 3136;
        int rem = warp % 3136;
        int win = rem / NTOK;
        int n   = rem % NTOK;
        int h_s = (win >> 3) * 7 + n / 7;
        int w_s = (win & 7) * 7 + n % 7;
        int hh = (h_s + 3) % 56;
        int ww = (w_s + 3) % 56;
        src = x + ((size_t)bb * 3136 + hh * 56 + ww) * CDIM;
    } else {
        src = x + (size_t)warp * CDIM;
    }

    float v[6];
    float s = 0.f, sq = 0.f;
    #pragma unroll
    for (int k = 0; k < 6; k++) {
        v[k] = src[lane + 32 * k];
        s += v[k];
        sq += v[k] * v[k];
    }
    #pragma unroll
    for (int o = 16; o; o >>= 1) {
        s  += __shfl_xor_sync(0xFFFFFFFFu, s, o);
        sq += __shfl_xor_sync(0xFFFFFFFFu, sq, o);
    }
    float mu  = s * (1.f / 192.f);
    float var = sq * (1.f / 192.f) - mu * mu;
    float rs  = rsqrtf(var + 1e-5f);

    __half* dst = out + (size_t)warp * CDIM;
    #pragma unroll
    for (int k = 0; k < 6; k++) {
        int c = lane + 32 * k;
        dst[c] = __float2half((v[k] - mu) * rs * gw[c] + gb[c]);
    }
}

// ================================================================
// Windowed attention (vectorized); fp32 qkv in, f16 ao out
// ================================================================
#define QSTR 36
__global__ void __launch_bounds__(256)
attn_kernel(const float* __restrict__ qkv,
            const float* __restrict__ rpb_table,
            __half* __restrict__ ao)
{
    __shared__ __align__(16) float qs[NTOK * QSTR];
    __shared__ __align__(16) float ks[NTOK * QSTR];
    __shared__ __align__(16) float vs[NTOK * QSTR];
    __shared__ float sc[NTOK][NTOK + 1];

    const int bid  = blockIdx.x;
    const int head = bid % NHEAD;
    const int win  = (bid / NHEAD) % NWIN;
    const int bb   = bid / (NHEAD * NWIN);
    const int tid  = threadIdx.x;

    const size_t baserow = (size_t)(bb * NWIN + win) * NTOK;

    for (int idx = tid; idx < NTOK * 8; idx += 256) {
        int n = idx >> 3, d4 = idx & 7;
        const float* p = qkv + (baserow + n) * QKVDIM + head * HDIM + d4 * 4;
        *(float4*)(qs + n * QSTR + d4 * 4) = *(const float4*)(p);
        *(float4*)(ks + n * QSTR + d4 * 4) = *(const float4*)(p + CDIM);
        *(float4*)(vs + n * QSTR + d4 * 4) = *(const float4*)(p + 2 * CDIM);
    }
    __syncthreads();

    const int wh = win >> 3, ww = win & 7;
    const float scale = 0.17677669529663687f;

    for (int idx = tid; idx < NTOK * NTOK; idx += 256) {
        int i = idx / NTOK, j = idx % NTOK;
        const float4* q4 = (const float4*)(qs + i * QSTR);
        const float4* k4 = (const float4*)(ks + j * QSTR);
        float s = 0.f;
        #pragma unroll
        for (int d = 0; d < 8; d++) {
            float4 a = q4[d], b = k4[d];
            s += a.x * b.x + a.y * b.y + a.z * b.z + a.w * b.w;
        }
        s *= scale;

        int ih = i / 7, iw = i % 7, jh = j / 7, jw = j % 7;
        s += rpb_table[((ih - jh + 6) * 13 + (iw - jw + 6)) * NHEAD + head];

        int hi = wh * 7 + ih, wi = ww * 7 + iw;
        int hj = wh * 7 + jh, wj = ww * 7 + jw;
        int ri = (hi < 49 ? 0 : (hi < 53 ? 1 : 2)) * 3 + (wi < 49 ? 0 : (wi < 53 ? 1 : 2));
        int rj = (hj < 49 ? 0 : (hj < 53 ? 1 : 2)) * 3 + (wj < 49 ? 0 : (wj < 53 ? 1 : 2));
        if (ri != rj) s -= 100.f;

        sc[i][j] = s;
    }
    __syncthreads();

    int warp = tid >> 5, lane = tid & 31;
    for (int i = warp; i < NTOK; i += 8) {
        float m = -1e30f;
        for (int j = lane; j < NTOK; j += 32) m = fmaxf(m, sc[i][j]);
        #pragma unroll
        for (int o = 16; o; o >>= 1) m = fmaxf(m, __shfl_xor_sync(0xFFFFFFFFu, m, o));
        float sum = 0.f;
        for (int j = lane; j < NTOK; j += 32) {
            float e = expf(sc[i][j] - m);
            sc[i][j] = e;
            sum += e;
        }
        #pragma unroll
        for (int o = 16; o; o >>= 1) sum += __shfl_xor_sync(0xFFFFFFFFu, sum, o);
        float inv = 1.f / sum;
        for (int j = lane; j < NTOK; j += 32) sc[i][j] *= inv;
    }
    __syncthreads();

    for (int idx = tid; idx < NTOK * 8; idx += 256) {
        int i = idx >> 3, d4 = idx & 7;
        float4 o = make_float4(0.f, 0.f, 0.f, 0.f);
        const float* sci = sc[i];
        #pragma unroll 7
        for (int j = 0; j < NTOK; j++) {
            float wv = sci[j];
            float4 v = *(const float4*)(vs + j * QSTR + d4 * 4);
            o.x += wv * v.x; o.y += wv * v.y; o.z += wv * v.z; o.w += wv * v.w;
        }
        __half2 h01 = __floats2half2_rn(o.x, o.y);
        __half2 h23 = __floats2half2_rn(o.z, o.w);
        __half2* dst = (__half2*)(ao + (baserow + i) * CDIM + head * HDIM + d4 * 4);
        dst[0] = h01;
        dst[1] = h23;
    }
}

// ================================================================
extern "C" void kernel_launch(void* const* d_in, const int* in_sizes, int n_in,
                              void* d_out, int out_size)
{
    const float* x       = (const float*)d_in[0];
    const float* norm1_g = (const float*)d_in[1];
    const float* norm1_b = (const float*)d_in[2];
    const float* qkv_w   = (const float*)d_in[3];
    const float* qkv_b   = (const float*)d_in[4];
    const float* rpb_t   = (const float*)d_in[5];
    const float* proj_w  = (const float*)d_in[6];
    const float* proj_b  = (const float*)d_in[7];
    const float* norm2_g = (const float*)d_in[8];
    const float* norm2_b = (const float*)d_in[9];
    const float* fc1_w   = (const float*)d_in[10];
    const float* fc1_b   = (const float*)d_in[11];
    const float* fc2_w   = (const float*)d_in[12];
    const float* fc2_b   = (const float*)d_in[13];
    float* out = (float*)d_out;

    __half *xw, *ao, *hbuf, *wt_qkv, *wt_proj, *wt_fc1, *wt_fc2;
    float *qkvbuf, *x1;
    cudaGetSymbolAddress((void**)&xw,      g_xw);
    cudaGetSymbolAddress((void**)&qkvbuf,  g_qkv);
    cudaGetSymbolAddress((void**)&ao,      g_ao);
    cudaGetSymbolAddress((void**)&x1,      g_x1);
    cudaGetSymbolAddress((void**)&hbuf,    g_h);
    cudaGetSymbolAddress((void**)&wt_qkv,  g_wt_qkv);
    cudaGetSymbolAddress((void**)&wt_proj, g_wt_proj);
    cudaGetSymbolAddress((void**)&wt_fc1,  g_wt_fc1);
    cudaGetSymbolAddress((void**)&wt_fc2,  g_wt_fc2);

    const int lnGrid = (NROWS + 7) / 8;

    // 0. Weight transposes -> [N][K] K-major f16
    transpose_kernel<<<(CDIM * QKVDIM + 255) / 256, 256>>>(qkv_w,  wt_qkv,  CDIM, QKVDIM);
    transpose_kernel<<<(CDIM * CDIM   + 255) / 256, 256>>>(proj_w, wt_proj, CDIM, CDIM);
    transpose_kernel<<<(CDIM * HID    + 255) / 256, 256>>>(fc1_w,  wt_fc1,  CDIM, HID);
    transpose_kernel<<<(HID  * CDIM   + 255) / 256, 256>>>(fc2_w,  wt_fc2,  HID,  CDIM);

    // 1. LN1 + shift + window partition (f16 out)
    ln_kernel<<<lnGrid, 256>>>(x, norm1_g, norm1_b, xw, 1);

    // 2. QKV GEMM [100352,192] @ [192,576] -> fp32 qkv
    mma_gemm<0><<<dim3(QKVDIM / 64, NROWS / 128), 128>>>(
        xw, wt_qkv, qkv_b, qkvbuf, nullptr, NROWS, QKVDIM, CDIM);

    // 3. Windowed attention -> f16 ao
    attn_kernel<<<32 * NWIN * NHEAD, 256>>>(qkvbuf, rpb_t, ao);

    // 4. Projection GEMM + fused un-shift/un-window + residual -> fp32 x1
    mma_gemm<3><<<dim3(CDIM / 64, NROWS / 128), 128>>>(
        ao, wt_proj, proj_b, x1, x, NROWS, CDIM, CDIM);

    // 5. LN2 (f16 out)
    ln_kernel<<<lnGrid, 256>>>(x1, norm2_g, norm2_b, xw, 0);

    // 6. FC1 + exact GELU [100352,192] @ [192,768] -> f16 hidden
    mma_gemm<1><<<dim3(HID / 64, NROWS / 128), 128>>>(
        xw, wt_fc1, fc1_b, hbuf, nullptr, NROWS, HID, CDIM);

    // 7. FC2 + residual [100352,768] @ [768,192] -> fp32 d_out
    mma_gemm<2><<<dim3(CDIM / 64, NROWS / 128), 128>>>(
        hbuf, wt_fc2, fc2_b, out, x1, NROWS, CDIM, HID);
}